// round 2
// baseline (speedup 1.0000x reference)
#include <cuda_runtime.h>
#include <math.h>

#define B_TOK 65536
#define D_DIM 4096
#define E_EXP 64
#define K_TOP 8

#define ROWS 32
#define COLS 128          // 64 gate cols + 64 noise cols
#define KT   32
#define NBLK (B_TOK / ROWS)   // 2048

// Deterministic per-block partials for the global softmax statistics.
__device__ double g_part_sum[NBLK];
__device__ double g_part_sq[NBLK];

__global__ __launch_bounds__(256, 2)
void gate_kernel(const float* __restrict__ x,
                 const float* __restrict__ wg,
                 const float* __restrict__ wn,
                 const float* __restrict__ noise,
                 float* __restrict__ out, int out_elems)
{
    __shared__ float xs[KT][ROWS + 1];            // +1 pad: conflict-free transposed stores
    __shared__ float ws[KT][COLS];                // weight tile; reused as eps[COLS][ROWS]
    __shared__ float res[ROWS][E_EXP + 1];        // noise staging, then output staging

    const int t    = threadIdx.x;
    const int rg   = t >> 5;                      // 0..7  (row group / warp id)
    const int cg   = t & 31;                      // 0..31 (col group)
    const int row0 = blockIdx.x * ROWS;

    float acc[4][4];
#pragma unroll
    for (int i = 0; i < 4; i++)
#pragma unroll
        for (int j = 0; j < 4; j++) acc[i][j] = 0.f;

    const int lr = t >> 3;                        // x-load row 0..31
    const int lk = (t & 7) << 2;                  // x-load k offset 0..28

    for (int k0 = 0; k0 < D_DIM; k0 += KT) {
        // ---- load x tile (coalesced float4, stored transposed) ----
        float4 xv = *(const float4*)(x + (size_t)(row0 + lr) * D_DIM + k0 + lk);
        xs[lk + 0][lr] = xv.x; xs[lk + 1][lr] = xv.y;
        xs[lk + 2][lr] = xv.z; xs[lk + 3][lr] = xv.w;

        // ---- load weight tile: cols 0..63 from w_gate, 64..127 from w_noise ----
#pragma unroll
        for (int i = 0; i < 4; i++) {
            int idx = t + (i << 8);               // 0..1023 float4s
            int kk  = idx >> 5;                   // 0..31
            int c4  = idx & 31;                   // 0..31  (c4<16 -> gate)
            const float* src = (c4 < 16)
                ? (wg + (size_t)(k0 + kk) * E_EXP + (c4 << 2))
                : (wn + (size_t)(k0 + kk) * E_EXP + ((c4 - 16) << 2));
            *(float4*)(&ws[kk][c4 << 2]) = *(const float4*)src;
        }
        __syncthreads();

        // ---- 4x4 outer-product FMA over the K chunk ----
#pragma unroll 8
        for (int kk = 0; kk < KT; kk++) {
            float a[4];
#pragma unroll
            for (int i = 0; i < 4; i++) a[i] = xs[kk][(rg << 2) + i];  // broadcast
            float4 bv = *(const float4*)(&ws[kk][cg << 2]);            // LDS.128
            float b[4] = {bv.x, bv.y, bv.z, bv.w};
#pragma unroll
            for (int i = 0; i < 4; i++)
#pragma unroll
                for (int j = 0; j < 4; j++)
                    acc[i][j] += a[i] * b[j];
        }
        __syncthreads();
    }

    // ---- stash tile column-major for the gating epilogue: eps[col][row] ----
    float (*eps)[ROWS] = reinterpret_cast<float(*)[ROWS]>(ws);
#pragma unroll
    for (int i = 0; i < 4; i++)
#pragma unroll
        for (int j = 0; j < 4; j++)
            eps[(cg << 2) + j][(rg << 2) + i] = acc[i][j];

    // ---- stage the noise rows coalesced ----
#pragma unroll
    for (int i = 0; i < 8; i++) {
        int idx = t + (i << 8);                   // 0..2047
        res[idx >> 6][idx & 63] = noise[(size_t)row0 * E_EXP + idx];
    }
    __syncthreads();

    double ps_d = 0.0, sq_d = 0.0;
    if (t < ROWS) {
        const int r = t;
        // logits = clean + noise * softplus(noise_logits); keep in eps[e][r]
        float m = -INFINITY;
        for (int e = 0; e < E_EXP; e++) {
            float c  = eps[e][r];
            float nr = eps[E_EXP + e][r];
            float sd = (nr > 20.f) ? nr : log1pf(expf(nr));
            float v  = c + res[r][e] * sd;
            eps[e][r] = v;
            m = fmaxf(m, v);
        }
        // full softmax statistics (for load loss)
        float s = 0.f;
        for (int e = 0; e < E_EXP; e++) s += expf(eps[e][r] - m);
        float inv = 1.f / s;
        float ps = 0.f, sq = 0.f;
        for (int e = 0; e < E_EXP; e++) {
            float p = expf(eps[e][r] - m) * inv;
            ps += p; sq += p * p;
        }
        ps_d = (double)ps; sq_d = (double)sq;

        // top-8 (strict > with ascending scan == jax lowest-index tie-break)
        unsigned long long sel = 0ULL;
        float m8 = 0.f;
        for (int kk = 0; kk < K_TOP; kk++) {
            float best = -INFINITY; int bi = 0;
            for (int e = 0; e < E_EXP; e++) {
                if (!((sel >> e) & 1ULL)) {
                    float v = eps[e][r];
                    if (v > best) { best = v; bi = e; }
                }
            }
            sel |= 1ULL << bi;
            if (kk == 0) m8 = best;
        }
        float s8 = 0.f;
        for (int e = 0; e < E_EXP; e++)
            if ((sel >> e) & 1ULL) s8 += expf(eps[e][r] - m8);
        float inv8 = 1.f / s8;
        for (int e = 0; e < E_EXP; e++)
            res[r][e] = ((sel >> e) & 1ULL) ? expf(eps[e][r] - m8) * inv8 : 0.f;
    }

    // warp 0 holds all 32 row partials -> deterministic per-block reduce
    if (t < 32) {
#pragma unroll
        for (int o = 16; o > 0; o >>= 1) {
            ps_d += __shfl_down_sync(0xffffffffu, ps_d, o);
            sq_d += __shfl_down_sync(0xffffffffu, sq_d, o);
        }
        if (t == 0) {
            g_part_sum[blockIdx.x] = ps_d;
            g_part_sq[blockIdx.x]  = sq_d;
        }
    }
    __syncthreads();

    // ---- coalesced output of router weights ----
#pragma unroll
    for (int i = 0; i < 8; i++) {
        int idx  = t + (i << 8);
        size_t o = (size_t)row0 * E_EXP + idx;
        if (o < (size_t)out_elems) out[o] = res[idx >> 6][idx & 63];
    }
}

__global__ void finalize_kernel(float* __restrict__ out, int out_elems)
{
    __shared__ double ssum[256], ssq[256];
    double a = 0.0, b = 0.0;
    for (int i = threadIdx.x; i < NBLK; i += 256) {
        a += g_part_sum[i];
        b += g_part_sq[i];
    }
    ssum[threadIdx.x] = a; ssq[threadIdx.x] = b;
    __syncthreads();
    for (int s = 128; s > 0; s >>= 1) {
        if (threadIdx.x < s) {
            ssum[threadIdx.x] += ssum[threadIdx.x + s];
            ssq[threadIdx.x]  += ssq[threadIdx.x + s];
        }
        __syncthreads();
    }
    if (threadIdx.x == 0) {
        double n    = (double)B_TOK * (double)E_EXP;
        double mean = ssum[0] / n;
        double var  = (ssq[0] - n * mean * mean) / (n - 1.0);   // ddof=1
        float loss  = (float)(var / (mean * mean + 1e-10));
        long long base = (long long)B_TOK * E_EXP;
        if (out_elems == 1) {
            out[0] = loss;                       // fallback: scalar-only output
        } else {
            for (long long i = base; i < (long long)out_elems; i++)
                out[i] = loss;                   // router_output then load_loss
        }
    }
}

extern "C" void kernel_launch(void* const* d_in, const int* in_sizes, int n_in,
                              void* d_out, int out_size)
{
    const float* x  = (const float*)d_in[0];
    const float* wg = (const float*)d_in[1];
    const float* wn = (const float*)d_in[2];
    const float* nz = (const float*)d_in[3];
    float* out = (float*)d_out;

    gate_kernel<<<NBLK, 256>>>(x, wg, wn, nz, out, out_size);
    finalize_kernel<<<1, 256>>>(out, out_size);
}

// round 4
// speedup vs baseline: 2.6938x; 2.6938x over previous
#include <cuda_runtime.h>
#include <cuda_fp16.h>
#include <math.h>
#include <stdint.h>

#define B_TOK 65536
#define D_DIM 4096
#define E_EXP 64
#define K_TOP 8

#define TM   128
#define NBLK (B_TOK / TM)        // 512 CTAs
#define KC   64                  // K per chunk
#define NCH  (D_DIM / KC)        // 64 chunks
#define NCOL 128                 // 64 gate + 64 noise columns fused

// w pre-split (scaled by 64 to keep lo parts in fp16 normal range), [n][k] K-major
__device__ __half g_wh[NCOL * D_DIM];
__device__ __half g_wl[NCOL * D_DIM];
__device__ double g_ps[NBLK];
__device__ double g_sq[NBLK];

// ---- smem byte layout ----
// mainloop: XH 0 (16KB) | XL 16384 | W buf0: H 32768, L 49152 | W buf1: H 65536, L 81920
// epilogue overlay (tiles dead): LG 0 (float[128][129]) | NSRS 66048 (float[128][65])
#define XH_OFF 0
#define XL_OFF 16384
#define W_OFF  32768
#define LG_OFF 0
#define NS_OFF 66048
#define SMEM_BYTES (66048 + 33280)   // 99328

static __device__ __forceinline__ uint32_t smem_u32(const void* p) {
    uint32_t a;
    asm("{ .reg .u64 t; cvta.to.shared.u64 t, %1; cvt.u32.u64 %0, t; }" : "=r"(a) : "l"(p));
    return a;
}
static __device__ __forceinline__ uint32_t sw128(uint32_t off) { return off ^ ((off >> 3) & 0x70); }
static __device__ __forceinline__ uint32_t pkh(__half a, __half b) {
    return (uint32_t)__half_as_ushort(a) | ((uint32_t)__half_as_ushort(b) << 16);
}

#define LDSM4(r, a) \
    asm volatile("ldmatrix.sync.aligned.m8n8.x4.shared.b16 {%0,%1,%2,%3}, [%4];" \
        : "=r"((r)[0]), "=r"((r)[1]), "=r"((r)[2]), "=r"((r)[3]) : "r"(a))

static __device__ __forceinline__ void mma16816(float* d, const uint32_t* a, uint32_t b0, uint32_t b1) {
    asm volatile("mma.sync.aligned.m16n8k16.row.col.f32.f16.f16.f32 "
        "{%0,%1,%2,%3}, {%4,%5,%6,%7}, {%8,%9}, {%0,%1,%2,%3};"
        : "+f"(d[0]), "+f"(d[1]), "+f"(d[2]), "+f"(d[3])
        : "r"(a[0]), "r"(a[1]), "r"(a[2]), "r"(a[3]), "r"(b0), "r"(b1));
}

#define CP_ASYNC16(dst, src) asm volatile("cp.async.cg.shared.global [%0], [%1], 16;" :: "r"(dst), "l"(src) : "memory")
#define CP_COMMIT()          asm volatile("cp.async.commit_group;" ::: "memory")
#define CP_WAIT1()           asm volatile("cp.async.wait_group 1;" ::: "memory")
#define CP_WAIT0()           asm volatile("cp.async.wait_group 0;" ::: "memory")

// ---- split w_gate|w_noise (x64) -> fp16 hi/lo, transposed to [n][k] ----
__global__ void wconv_kernel(const float* __restrict__ wg, const float* __restrict__ wn)
{
    int idx = blockIdx.x * 256 + threadIdx.x;     // over D*E
    if (idx >= D_DIM * E_EXP) return;
    int k = idx >> 6, n = idx & 63;
    float f = wg[idx] * 64.f;
    __half h = __float2half(f);
    g_wh[(size_t)n * D_DIM + k] = h;
    g_wl[(size_t)n * D_DIM + k] = __float2half(f - __half2float(h));
    f = wn[idx] * 64.f;
    h = __float2half(f);
    g_wh[(size_t)(64 + n) * D_DIM + k] = h;
    g_wl[(size_t)(64 + n) * D_DIM + k] = __float2half(f - __half2float(h));
}

static __device__ __forceinline__ void load_x_regs(const float* xp, int k0, int t, float4 (&xr)[8]) {
#pragma unroll
    for (int i = 0; i < 8; i++) {
        int idx = t + (i << 8);
        int r = idx >> 4, j = idx & 15;
        xr[i] = *(const float4*)(xp + (size_t)r * D_DIM + k0 + (j << 2));
    }
}
static __device__ __forceinline__ void store_x_smem(char* smem, int t, const float4 (&xr)[8]) {
#pragma unroll
    for (int i = 0; i < 8; i++) {
        int idx = t + (i << 8);
        int r = idx >> 4, j = idx & 15;
        float4 v = xr[i];
        __half h0 = __float2half(v.x), h1 = __float2half(v.y);
        __half h2 = __float2half(v.z), h3 = __float2half(v.w);
        __half l0 = __float2half(v.x - __half2float(h0)), l1 = __float2half(v.y - __half2float(h1));
        __half l2 = __float2half(v.z - __half2float(h2)), l3 = __float2half(v.w - __half2float(h3));
        uint32_t sw = sw128((r << 7) + (j << 3));
        *(uint2*)(smem + XH_OFF + sw) = make_uint2(pkh(h0, h1), pkh(h2, h3));
        *(uint2*)(smem + XL_OFF + sw) = make_uint2(pkh(l0, l1), pkh(l2, l3));
    }
}
static __device__ __forceinline__ void issue_w(uint32_t sb, int t, int k0, int buf) {
    uint32_t base = sb + W_OFF + buf * 32768;
#pragma unroll
    for (int i = 0; i < 8; i++) {
        int idx = t + (i << 8);                  // 0..2047
        int v = i >> 2;                          // 0: hi (i<4), 1: lo
        int rem = idx & 1023;
        int n = rem >> 3, q = rem & 7;
        const __half* src = (v ? g_wl : g_wh) + (size_t)n * D_DIM + k0 + (q << 3);
        uint32_t dst = base + v * 16384 + sw128((n << 7) + (q << 4));
        CP_ASYNC16(dst, src);
    }
}

__global__ __launch_bounds__(256, 1)
void gate_mma_kernel(const float* __restrict__ x,
                     const float* __restrict__ noise,
                     float* __restrict__ out, int out_elems)
{
    extern __shared__ char smem[];
    const uint32_t sb = smem_u32(smem);
    const int t   = threadIdx.x;
    const int wid = t >> 5;
    const int lid = t & 31;
    const int wm  = wid & 1;          // 64-row group
    const int wn  = wid >> 1;         // 32-col group
    const int row0 = blockIdx.x * TM;
    const float* xp = x + (size_t)row0 * D_DIM;

    float acc[4][4][4];
#pragma unroll
    for (int a = 0; a < 4; a++)
#pragma unroll
        for (int b = 0; b < 4; b++)
#pragma unroll
            for (int c = 0; c < 4; c++) acc[a][b][c] = 0.f;

    // per-lane ldmatrix addressing (xor mask depends only on lid&7)
    const uint32_t xmask     = (uint32_t)(lid & 7) << 4;
    const uint32_t a_rowbase = (uint32_t)(wm * 64 + ((lid >> 3) & 1) * 8 + (lid & 7)) * 128;
    const uint32_t a_kincr   = (uint32_t)(lid >> 4) * 16;
    const uint32_t b_rowbase = (uint32_t)(wn * 32 + ((lid >> 4) << 3) + (lid & 7)) * 128;
    const uint32_t b_kincr   = (uint32_t)((lid >> 3) & 1) * 16;

    float4 xr[8];
    issue_w(sb, t, 0, 0); CP_COMMIT();
    load_x_regs(xp, 0, t, xr);

    for (int c = 0; c < NCH; ++c) {
        __syncthreads();                          // x smem consumers of chunk c-1 done
        store_x_smem(smem, t, xr);
        if (c < NCH - 1) { issue_w(sb, t, (c + 1) * KC, (c + 1) & 1); CP_COMMIT(); }
        if (c < NCH - 1) CP_WAIT1(); else CP_WAIT0();
        __syncthreads();
        if (c < NCH - 1) load_x_regs(xp, (c + 1) * KC, t, xr);

        const uint32_t wb = sb + W_OFF + (c & 1) * 32768;
#pragma unroll
        for (int ks = 0; ks < 4; ++ks) {
            const uint32_t aoff = (uint32_t)(ks * 32 + a_kincr) ^ xmask;
            uint32_t aH[4][4], aL[4][4];
#pragma unroll
            for (int mt = 0; mt < 4; ++mt) {
                LDSM4(aH[mt], sb + XH_OFF + a_rowbase + mt * 2048 + aoff);
                LDSM4(aL[mt], sb + XL_OFF + a_rowbase + mt * 2048 + aoff);
            }
            const uint32_t boff = (uint32_t)(ks * 32 + b_kincr) ^ xmask;
            uint32_t bH[8], bL[8];
#pragma unroll
            for (int g = 0; g < 2; ++g) {
                LDSM4(&bH[g * 4], wb + b_rowbase + g * 2048 + boff);
                LDSM4(&bL[g * 4], wb + 16384 + b_rowbase + g * 2048 + boff);
            }
#pragma unroll
            for (int mt = 0; mt < 4; ++mt)
#pragma unroll
                for (int nt = 0; nt < 4; ++nt) {
                    int bi = (nt >> 1) * 4 + (nt & 1) * 2;
                    mma16816(acc[mt][nt], aH[mt], bH[bi], bH[bi + 1]);
                    mma16816(acc[mt][nt], aH[mt], bL[bi], bL[bi + 1]);
                    mma16816(acc[mt][nt], aL[mt], bH[bi], bH[bi + 1]);
                }
        }
    }

    // ================= epilogue =================
    __syncthreads();                              // all MMAs done; tiles dead
    float* lg   = (float*)(smem + LG_OFF);        // [128][129] scaled logits (clean|noise)
    float* nsrs = (float*)(smem + NS_OFF);        // [128][65]  noise, then router probs

#pragma unroll
    for (int i = 0; i < 32; i++) {
        int idx = t + (i << 8);
        nsrs[(idx >> 6) * 65 + (idx & 63)] = noise[(size_t)row0 * E_EXP + idx];
    }
#pragma unroll
    for (int mt = 0; mt < 4; ++mt) {
        int r = wm * 64 + mt * 16 + (lid >> 2);
#pragma unroll
        for (int nt = 0; nt < 4; ++nt) {
            int c0 = wn * 32 + nt * 8 + (lid & 3) * 2;
            lg[r * 129 + c0]           = acc[mt][nt][0];
            lg[r * 129 + c0 + 1]       = acc[mt][nt][1];
            lg[(r + 8) * 129 + c0]     = acc[mt][nt][2];
            lg[(r + 8) * 129 + c0 + 1] = acc[mt][nt][3];
        }
    }
    __syncthreads();

    double ps_d = 0.0, sq_d = 0.0;
    if (t < TM) {
        const int r = t;
        float m = -INFINITY;
        for (int e = 0; e < E_EXP; ++e) {
            float cl = lg[r * 129 + e]      * 0.015625f;   // undo w*64 scale
            float nr = lg[r * 129 + 64 + e] * 0.015625f;
            float sd = (nr > 20.f) ? nr : log1pf(__expf(nr));
            float v  = cl + nsrs[r * 65 + e] * sd;
            lg[r * 129 + e] = v;
            m = fmaxf(m, v);
        }
        float s = 0.f;
        for (int e = 0; e < E_EXP; ++e) s += __expf(lg[r * 129 + e] - m);
        float inv = 1.f / s;
        float ps = 0.f, sq = 0.f;
        for (int e = 0; e < E_EXP; ++e) {
            float p = __expf(lg[r * 129 + e] - m) * inv;
            ps += p; sq += p * p;
        }
        ps_d = ps; sq_d = sq;

        unsigned long long sel = 0ULL;
        float m8 = 0.f;
        for (int kk = 0; kk < K_TOP; ++kk) {
            float best = -INFINITY; int bi = 0;
            for (int e = 0; e < E_EXP; ++e) {
                if (!((sel >> e) & 1ULL)) {
                    float v = lg[r * 129 + e];
                    if (v > best) { best = v; bi = e; }
                }
            }
            sel |= 1ULL << bi;
            if (kk == 0) m8 = best;
        }
        float s8 = 0.f;
        for (int e = 0; e < E_EXP; ++e)
            if ((sel >> e) & 1ULL) s8 += __expf(lg[r * 129 + e] - m8);
        float inv8 = 1.f / s8;
        for (int e = 0; e < E_EXP; ++e)
            nsrs[r * 65 + e] = ((sel >> e) & 1ULL) ? __expf(lg[r * 129 + e] - m8) * inv8 : 0.f;
    }

    __shared__ double wps[4], wsq[4];
#pragma unroll
    for (int o = 16; o > 0; o >>= 1) {
        ps_d += __shfl_down_sync(0xffffffffu, ps_d, o);
        sq_d += __shfl_down_sync(0xffffffffu, sq_d, o);
    }
    if (wid < 4 && lid == 0) { wps[wid] = ps_d; wsq[wid] = sq_d; }
    __syncthreads();
    if (t == 0) {
        g_ps[blockIdx.x] = wps[0] + wps[1] + wps[2] + wps[3];
        g_sq[blockIdx.x] = wsq[0] + wsq[1] + wsq[2] + wsq[3];
    }
#pragma unroll
    for (int i = 0; i < 32; i++) {
        int idx = t + (i << 8);
        size_t o = (size_t)row0 * E_EXP + idx;
        if (o < (size_t)out_elems) out[o] = nsrs[(idx >> 6) * 65 + (idx & 63)];
    }
}

__global__ void finalize_kernel(float* __restrict__ out, int out_elems)
{
    __shared__ double ssum[256], ssq[256];
    double a = 0.0, b = 0.0;
    for (int i = threadIdx.x; i < NBLK; i += 256) { a += g_ps[i]; b += g_sq[i]; }
    ssum[threadIdx.x] = a; ssq[threadIdx.x] = b;
    __syncthreads();
    for (int s = 128; s > 0; s >>= 1) {
        if (threadIdx.x < s) {
            ssum[threadIdx.x] += ssum[threadIdx.x + s];
            ssq[threadIdx.x]  += ssq[threadIdx.x + s];
        }
        __syncthreads();
    }
    if (threadIdx.x == 0) {
        double n    = (double)B_TOK * (double)E_EXP;
        double mean = ssum[0] / n;
        double var  = (ssq[0] - n * mean * mean) / (n - 1.0);
        float loss  = (float)(var / (mean * mean + 1e-10));
        long long base = (long long)B_TOK * E_EXP;
        if (out_elems == 1) out[0] = loss;
        else for (long long i = base; i < (long long)out_elems; i++) out[i] = loss;
    }
}

extern "C" void kernel_launch(void* const* d_in, const int* in_sizes, int n_in,
                              void* d_out, int out_size)
{
    const float* x  = (const float*)d_in[0];
    const float* wg = (const float*)d_in[1];
    const float* wn = (const float*)d_in[2];
    const float* nz = (const float*)d_in[3];
    float* out = (float*)d_out;

    cudaFuncSetAttribute(gate_mma_kernel, cudaFuncAttributeMaxDynamicSharedMemorySize, SMEM_BYTES);

    wconv_kernel<<<(D_DIM * E_EXP + 255) / 256, 256>>>(wg, wn);
    gate_mma_kernel<<<NBLK, 256, SMEM_BYTES>>>(x, nz, out, out_size);
    finalize_kernel<<<1, 256>>>(out, out_size);
}

// round 5
// speedup vs baseline: 3.1545x; 1.1710x over previous
#include <cuda_runtime.h>
#include <cuda_fp16.h>
#include <math.h>
#include <stdint.h>

#define B_TOK 65536
#define D_DIM 4096
#define E_EXP 64
#define K_TOP 8

#define TM   128
#define NBLK (B_TOK / TM)        // 512 CTAs
#define KC   64                  // K per chunk
#define NCH  (D_DIM / KC)        // 64 chunks
#define NCOL 128                 // 64 gate + 64 noise columns fused

// w pre-split (scaled by 64 to keep lo parts in fp16 normal range), [n][k] K-major
__device__ __half g_wh[NCOL * D_DIM];
__device__ __half g_wl[NCOL * D_DIM];
__device__ double g_ps[NBLK];
__device__ double g_sq[NBLK];

// ---- smem byte layout ----
// mainloop: XH 0 (16KB) | XL 16384 | W buf0: H 32768, L 49152 | W buf1: H 65536, L 81920
// epilogue overlay (tiles dead): LG 0 (float[128][129]) | NSRS 66048 (float[128][65])
#define XH_OFF 0
#define XL_OFF 16384
#define W_OFF  32768
#define LG_OFF 0
#define NS_OFF 66048
#define SMEM_BYTES (66048 + 33280)   // 99328; 2 CTAs/SM = 194KB < 228KB

static __device__ __forceinline__ uint32_t smem_u32(const void* p) {
    uint32_t a;
    asm("{ .reg .u64 t; cvta.to.shared.u64 t, %1; cvt.u32.u64 %0, t; }" : "=r"(a) : "l"(p));
    return a;
}
static __device__ __forceinline__ uint32_t sw128(uint32_t off) { return off ^ ((off >> 3) & 0x70); }
static __device__ __forceinline__ uint32_t pkh(__half a, __half b) {
    return (uint32_t)__half_as_ushort(a) | ((uint32_t)__half_as_ushort(b) << 16);
}

#define LDSM4(r, a) \
    asm volatile("ldmatrix.sync.aligned.m8n8.x4.shared.b16 {%0,%1,%2,%3}, [%4];" \
        : "=r"((r)[0]), "=r"((r)[1]), "=r"((r)[2]), "=r"((r)[3]) : "r"(a))

static __device__ __forceinline__ void mma16816(float* d, const uint32_t* a, uint32_t b0, uint32_t b1) {
    asm volatile("mma.sync.aligned.m16n8k16.row.col.f32.f16.f16.f32 "
        "{%0,%1,%2,%3}, {%4,%5,%6,%7}, {%8,%9}, {%0,%1,%2,%3};"
        : "+f"(d[0]), "+f"(d[1]), "+f"(d[2]), "+f"(d[3])
        : "r"(a[0]), "r"(a[1]), "r"(a[2]), "r"(a[3]), "r"(b0), "r"(b1));
}

#define CP_ASYNC16(dst, src) asm volatile("cp.async.cg.shared.global [%0], [%1], 16;" :: "r"(dst), "l"(src) : "memory")
#define CP_COMMIT()          asm volatile("cp.async.commit_group;" ::: "memory")
#define CP_WAIT1()           asm volatile("cp.async.wait_group 1;" ::: "memory")
#define CP_WAIT0()           asm volatile("cp.async.wait_group 0;" ::: "memory")

// ---- split w_gate|w_noise (x64) -> fp16 hi/lo, transposed to [n][k] ----
__global__ void wconv_kernel(const float* __restrict__ wg, const float* __restrict__ wn)
{
    int idx = blockIdx.x * 256 + threadIdx.x;     // over D*E
    if (idx >= D_DIM * E_EXP) return;
    int k = idx >> 6, n = idx & 63;
    float f = wg[idx] * 64.f;
    __half h = __float2half(f);
    g_wh[(size_t)n * D_DIM + k] = h;
    g_wl[(size_t)n * D_DIM + k] = __float2half(f - __half2float(h));
    f = wn[idx] * 64.f;
    h = __float2half(f);
    g_wh[(size_t)(64 + n) * D_DIM + k] = h;
    g_wl[(size_t)(64 + n) * D_DIM + k] = __float2half(f - __half2float(h));
}

static __device__ __forceinline__ void issue_w(uint32_t sb, int t, int k0, int buf) {
    uint32_t base = sb + W_OFF + buf * 32768;
#pragma unroll
    for (int i = 0; i < 8; i++) {
        int idx = t + (i << 8);                  // 0..2047
        int v = i >> 2;                          // 0: hi (i<4), 1: lo
        int rem = idx & 1023;
        int n = rem >> 3, q = rem & 7;
        const __half* src = (v ? g_wl : g_wh) + (size_t)n * D_DIM + k0 + (q << 3);
        uint32_t dst = base + v * 16384 + sw128((n << 7) + (q << 4));
        CP_ASYNC16(dst, src);
    }
}

__global__ __launch_bounds__(256, 2)
void gate_mma_kernel(const float* __restrict__ x,
                     const float* __restrict__ noise,
                     float* __restrict__ out, int out_elems)
{
    extern __shared__ char smem[];
    const uint32_t sb = smem_u32(smem);
    const int t   = threadIdx.x;
    const int wid = t >> 5;
    const int lid = t & 31;
    const int wm  = wid & 1;          // 64-row group
    const int wn  = wid >> 1;         // 32-col group
    const int row0 = blockIdx.x * TM;
    const float* xp = x + (size_t)row0 * D_DIM;

    float acc[4][4][4];
#pragma unroll
    for (int a = 0; a < 4; a++)
#pragma unroll
        for (int b = 0; b < 4; b++)
#pragma unroll
            for (int c = 0; c < 4; c++) acc[a][b][c] = 0.f;

    // per-lane ldmatrix addressing (xor mask depends only on lid&7)
    const uint32_t xmask     = (uint32_t)(lid & 7) << 4;
    const uint32_t a_rowbase = (uint32_t)(wm * 64 + ((lid >> 3) & 1) * 8 + (lid & 7)) * 128;
    const uint32_t a_kincr   = (uint32_t)(lid >> 4) * 16;
    const uint32_t b_rowbase = (uint32_t)(wn * 32 + ((lid >> 4) << 3) + (lid & 7)) * 128;
    const uint32_t b_kincr   = (uint32_t)((lid >> 3) & 1) * 16;

    // per-thread x tile coords (each thread: 8 float4 per chunk)
    const int xr_ = t >> 4;                // row 0..15 base (x16 stride below)
    const int xj_ = t & 15;                // float4 col

    issue_w(sb, t, 0, 0); CP_COMMIT();

    for (int c = 0; c < NCH; ++c) {
        const int k0 = c * KC;
        __syncthreads();                  // x smem + W buf (c+1)&1 consumers done
        // ---- load x fp32, split to fp16 hi/lo, store swizzled ----
#pragma unroll
        for (int i = 0; i < 8; ++i) {
            int r = xr_ + (i << 4);
            float4 v = *(const float4*)(xp + (size_t)r * D_DIM + k0 + (xj_ << 2));
            __half h0 = __float2half(v.x), h1 = __float2half(v.y);
            __half h2 = __float2half(v.z), h3 = __float2half(v.w);
            __half l0 = __float2half(v.x - __half2float(h0)), l1 = __float2half(v.y - __half2float(h1));
            __half l2 = __float2half(v.z - __half2float(h2)), l3 = __float2half(v.w - __half2float(h3));
            uint32_t sw = sw128((r << 7) + (xj_ << 3));
            *(uint2*)(smem + XH_OFF + sw) = make_uint2(pkh(h0, h1), pkh(h2, h3));
            *(uint2*)(smem + XL_OFF + sw) = make_uint2(pkh(l0, l1), pkh(l2, l3));
        }
        if (c < NCH - 1) { issue_w(sb, t, (c + 1) * KC, (c + 1) & 1); CP_COMMIT(); CP_WAIT1(); }
        else             { CP_WAIT0(); }
        __syncthreads();

        const uint32_t wb = sb + W_OFF + (c & 1) * 32768;
#pragma unroll
        for (int ks = 0; ks < 4; ++ks) {
            const uint32_t boff = (uint32_t)(ks * 32 + b_kincr) ^ xmask;
            uint32_t bH[8], bL[8];
            LDSM4(&bH[0], wb + b_rowbase + boff);
            LDSM4(&bH[4], wb + b_rowbase + 2048 + boff);
            LDSM4(&bL[0], wb + 16384 + b_rowbase + boff);
            LDSM4(&bL[4], wb + 16384 + b_rowbase + 2048 + boff);
            const uint32_t aoff = (uint32_t)(ks * 32 + a_kincr) ^ xmask;
#pragma unroll
            for (int mt = 0; mt < 4; ++mt) {
                uint32_t aH[4], aL[4];
                LDSM4(aH, sb + XH_OFF + a_rowbase + mt * 2048 + aoff);
                LDSM4(aL, sb + XL_OFF + a_rowbase + mt * 2048 + aoff);
#pragma unroll
                for (int nt = 0; nt < 4; ++nt) {
                    int bi = (nt >> 1) * 4 + (nt & 1) * 2;
                    mma16816(acc[mt][nt], aH, bH[bi], bH[bi + 1]);
                    mma16816(acc[mt][nt], aH, bL[bi], bL[bi + 1]);
                    mma16816(acc[mt][nt], aL, bH[bi], bH[bi + 1]);
                }
            }
        }
    }

    // ================= epilogue =================
    __syncthreads();                              // all MMAs done; tiles dead
    float* lg   = (float*)(smem + LG_OFF);        // [128][129] scaled logits (clean|noise)
    float* nsrs = (float*)(smem + NS_OFF);        // [128][65]  noise, then router probs

#pragma unroll
    for (int i = 0; i < 32; i++) {
        int idx = t + (i << 8);
        nsrs[(idx >> 6) * 65 + (idx & 63)] = noise[(size_t)row0 * E_EXP + idx];
    }
#pragma unroll
    for (int mt = 0; mt < 4; ++mt) {
        int r = wm * 64 + mt * 16 + (lid >> 2);
#pragma unroll
        for (int nt = 0; nt < 4; ++nt) {
            int c0 = wn * 32 + nt * 8 + (lid & 3) * 2;
            lg[r * 129 + c0]           = acc[mt][nt][0];
            lg[r * 129 + c0 + 1]       = acc[mt][nt][1];
            lg[(r + 8) * 129 + c0]     = acc[mt][nt][2];
            lg[(r + 8) * 129 + c0 + 1] = acc[mt][nt][3];
        }
    }
    __syncthreads();

    double ps_d = 0.0, sq_d = 0.0;
    if (t < TM) {
        const int r = t;
        float m = -INFINITY;
        for (int e = 0; e < E_EXP; ++e) {
            float cl = lg[r * 129 + e]      * 0.015625f;   // undo w*64 scale
            float nr = lg[r * 129 + 64 + e] * 0.015625f;
            float sd = (nr > 20.f) ? nr : log1pf(__expf(nr));
            float v  = cl + nsrs[r * 65 + e] * sd;
            lg[r * 129 + e] = v;
            m = fmaxf(m, v);
        }
        float s = 0.f;
        for (int e = 0; e < E_EXP; ++e) s += __expf(lg[r * 129 + e] - m);
        float inv = 1.f / s;
        float ps = 0.f, sq = 0.f;
        for (int e = 0; e < E_EXP; ++e) {
            float p = __expf(lg[r * 129 + e] - m) * inv;
            ps += p; sq += p * p;
        }
        ps_d = ps; sq_d = sq;

        unsigned long long sel = 0ULL;
        float m8 = 0.f;
        for (int kk = 0; kk < K_TOP; ++kk) {
            float best = -INFINITY; int bi = 0;
            for (int e = 0; e < E_EXP; ++e) {
                if (!((sel >> e) & 1ULL)) {
                    float v = lg[r * 129 + e];
                    if (v > best) { best = v; bi = e; }
                }
            }
            sel |= 1ULL << bi;
            if (kk == 0) m8 = best;
        }
        float s8 = 0.f;
        for (int e = 0; e < E_EXP; ++e)
            if ((sel >> e) & 1ULL) s8 += __expf(lg[r * 129 + e] - m8);
        float inv8 = 1.f / s8;
        for (int e = 0; e < E_EXP; ++e)
            nsrs[r * 65 + e] = ((sel >> e) & 1ULL) ? __expf(lg[r * 129 + e] - m8) * inv8 : 0.f;
    }

    __shared__ double wps[4], wsq[4];
#pragma unroll
    for (int o = 16; o > 0; o >>= 1) {
        ps_d += __shfl_down_sync(0xffffffffu, ps_d, o);
        sq_d += __shfl_down_sync(0xffffffffu, sq_d, o);
    }
    if (wid < 4 && lid == 0) { wps[wid] = ps_d; wsq[wid] = sq_d; }
    __syncthreads();
    if (t == 0) {
        g_ps[blockIdx.x] = wps[0] + wps[1] + wps[2] + wps[3];
        g_sq[blockIdx.x] = wsq[0] + wsq[1] + wsq[2] + wsq[3];
    }
#pragma unroll
    for (int i = 0; i < 32; i++) {
        int idx = t + (i << 8);
        size_t o = (size_t)row0 * E_EXP + idx;
        if (o < (size_t)out_elems) out[o] = nsrs[(idx >> 6) * 65 + (idx & 63)];
    }
}

__global__ void finalize_kernel(float* __restrict__ out, int out_elems)
{
    __shared__ double ssum[256], ssq[256];
    double a = 0.0, b = 0.0;
    for (int i = threadIdx.x; i < NBLK; i += 256) { a += g_ps[i]; b += g_sq[i]; }
    ssum[threadIdx.x] = a; ssq[threadIdx.x] = b;
    __syncthreads();
    for (int s = 128; s > 0; s >>= 1) {
        if (threadIdx.x < s) {
            ssum[threadIdx.x] += ssum[threadIdx.x + s];
            ssq[threadIdx.x]  += ssq[threadIdx.x + s];
        }
        __syncthreads();
    }
    if (threadIdx.x == 0) {
        double n    = (double)B_TOK * (double)E_EXP;
        double mean = ssum[0] / n;
        double var  = (ssq[0] - n * mean * mean) / (n - 1.0);
        float loss  = (float)(var / (mean * mean + 1e-10));
        long long base = (long long)B_TOK * E_EXP;
        if (out_elems == 1) out[0] = loss;
        else for (long long i = base; i < (long long)out_elems; i++) out[i] = loss;
    }
}

extern "C" void kernel_launch(void* const* d_in, const int* in_sizes, int n_in,
                              void* d_out, int out_size)
{
    const float* x  = (const float*)d_in[0];
    const float* wg = (const float*)d_in[1];
    const float* wn = (const float*)d_in[2];
    const float* nz = (const float*)d_in[3];
    float* out = (float*)d_out;

    cudaFuncSetAttribute(gate_mma_kernel, cudaFuncAttributeMaxDynamicSharedMemorySize, SMEM_BYTES);

    wconv_kernel<<<(D_DIM * E_EXP + 255) / 256, 256>>>(wg, wn);
    gate_mma_kernel<<<NBLK, 256, SMEM_BYTES>>>(x, nz, out, out_size);
    finalize_kernel<<<1, 256>>>(out, out_size);
}